// round 3
// baseline (speedup 1.0000x reference)
#include <cuda_runtime.h>
#include <mma.h>

using namespace nvcuda;

#define HIDDEN 768
#define BATCH  4
#define SEQ    4096

// ---- scratch (device globals: allocation-free rule) ----
__device__ float g_Q[BATCH * SEQ * HIDDEN];                 // 48 MB
__device__ float g_K[BATCH * SEQ * HIDDEN];                 // 48 MB
__device__ float g_V[BATCH * SEQ * HIDDEN];                 // 48 MB
__device__ float g_S[(long long)BATCH * SEQ * SEQ];         // 256 MB

// ---------------------------------------------------------------------------
// Generic TF32 wmma GEMM:  C = A @ B
//   A: row-major [M,K]
//   B_COL=true : B stored [N,K] row-major, i.e. logical B[k,n] = Bmem[n*K+k]
//   B_COL=false: B stored [K,N] row-major, i.e. logical B[k,n] = Bmem[k*N+n]
// Block tile 128x128x32, 256 threads (8 warps, 2x4), warp tile 64x32.
// ---------------------------------------------------------------------------
constexpr int BM = 128, BN = 128, BK = 32;
constexpr int BKP = 36;   // padded leading dim for k-contiguous smem tiles
constexpr int BNP = 132;  // padded leading dim for n-contiguous smem tiles

template <bool B_COL>
__global__ __launch_bounds__(256, 2)
void gemm_kernel(const float* __restrict__ A,
                 const float* __restrict__ B,
                 float* __restrict__ C,
                 int M, int N, int K,
                 long long strideA, long long strideB, long long strideC)
{
    __shared__ float As[BM * BKP];       // [128][36]
    __shared__ float Bs[BN * BKP];       // col: [128][36] / row: [32][132] (fits)

    A += (long long)blockIdx.z * strideA;
    B += (long long)blockIdx.z * strideB;
    C += (long long)blockIdx.z * strideC;

    const int m0 = blockIdx.y * BM;
    const int n0 = blockIdx.x * BN;
    const int tid  = threadIdx.x;
    const int warp = tid >> 5;
    const int wm = (warp >> 2) * 64;     // warp row offset: 0 / 64
    const int wn = (warp & 3) * 32;      // warp col offset: 0/32/64/96

    wmma::fragment<wmma::accumulator, 16, 16, 8, float> acc[4][2];
#pragma unroll
    for (int i = 0; i < 4; i++)
#pragma unroll
        for (int j = 0; j < 2; j++)
            wmma::fill_fragment(acc[i][j], 0.0f);

    for (int k0 = 0; k0 < K; k0 += BK) {
        // ---- load A tile [128 x 32], k-contiguous float4 ----
#pragma unroll
        for (int i = 0; i < 4; i++) {
            int idx = tid + i * 256;
            int r = idx >> 3;
            int c = (idx & 7) << 2;
            float4 v = *reinterpret_cast<const float4*>(
                A + (long long)(m0 + r) * K + k0 + c);
            *reinterpret_cast<float4*>(&As[r * BKP + c]) = v;
        }
        // ---- load B tile ----
        if (B_COL) {
            // Bmem[n*K + k]: k-contiguous per n row
#pragma unroll
            for (int i = 0; i < 4; i++) {
                int idx = tid + i * 256;
                int r = idx >> 3;           // n within tile
                int c = (idx & 7) << 2;     // k within tile
                float4 v = *reinterpret_cast<const float4*>(
                    B + (long long)(n0 + r) * K + k0 + c);
                *reinterpret_cast<float4*>(&Bs[r * BKP + c]) = v;
            }
        } else {
            // Bmem[k*N + n]: n-contiguous per k row
#pragma unroll
            for (int i = 0; i < 4; i++) {
                int idx = tid + i * 256;
                int r = idx >> 5;           // k within tile (0..31)
                int c = (idx & 31) << 2;    // n within tile (0..124)
                float4 v = *reinterpret_cast<const float4*>(
                    B + (long long)(k0 + r) * N + n0 + c);
                *reinterpret_cast<float4*>(&Bs[r * BNP + c]) = v;
            }
        }
        __syncthreads();

        // ---- compute ----
#pragma unroll
        for (int kk = 0; kk < BK; kk += 8) {
            wmma::fragment<wmma::matrix_a, 16, 16, 8,
                           wmma::precision::tf32, wmma::row_major> af[4];
#pragma unroll
            for (int i = 0; i < 4; i++) {
                wmma::load_matrix_sync(af[i], &As[(wm + i * 16) * BKP + kk], BKP);
#pragma unroll
                for (int t = 0; t < af[i].num_elements; t++)
                    af[i].x[t] = wmma::__float_to_tf32(af[i].x[t]);
            }
            if constexpr (B_COL) {
                wmma::fragment<wmma::matrix_b, 16, 16, 8,
                               wmma::precision::tf32, wmma::col_major> bf[2];
#pragma unroll
                for (int j = 0; j < 2; j++) {
                    wmma::load_matrix_sync(bf[j], &Bs[(wn + j * 16) * BKP + kk], BKP);
#pragma unroll
                    for (int t = 0; t < bf[j].num_elements; t++)
                        bf[j].x[t] = wmma::__float_to_tf32(bf[j].x[t]);
                }
#pragma unroll
                for (int i = 0; i < 4; i++)
#pragma unroll
                    for (int j = 0; j < 2; j++)
                        wmma::mma_sync(acc[i][j], af[i], bf[j], acc[i][j]);
            } else {
                wmma::fragment<wmma::matrix_b, 16, 16, 8,
                               wmma::precision::tf32, wmma::row_major> bf[2];
#pragma unroll
                for (int j = 0; j < 2; j++) {
                    wmma::load_matrix_sync(bf[j], &Bs[kk * BNP + wn + j * 16], BNP);
#pragma unroll
                    for (int t = 0; t < bf[j].num_elements; t++)
                        bf[j].x[t] = wmma::__float_to_tf32(bf[j].x[t]);
                }
#pragma unroll
                for (int i = 0; i < 4; i++)
#pragma unroll
                    for (int j = 0; j < 2; j++)
                        wmma::mma_sync(acc[i][j], af[i], bf[j], acc[i][j]);
            }
        }
        __syncthreads();
    }

    // ---- epilogue ----
#pragma unroll
    for (int i = 0; i < 4; i++)
#pragma unroll
        for (int j = 0; j < 2; j++) {
            float* cptr = C + (long long)(m0 + wm + i * 16) * N + (n0 + wn + j * 16);
            wmma::store_matrix_sync(cptr, acc[i][j], N, wmma::mem_row_major);
        }
}

// ---------------------------------------------------------------------------
// Bias add: Y[r, c] += b[c], vectorized float4 (HIDDEN % 4 == 0)
// ---------------------------------------------------------------------------
__global__ void bias_kernel(float4* __restrict__ Y, const float* __restrict__ b, int n4)
{
    int i = blockIdx.x * blockDim.x + threadIdx.x;
    if (i >= n4) return;
    int col = (i % (HIDDEN / 4)) * 4;
    float4 v = Y[i];
    v.x += b[col + 0];
    v.y += b[col + 1];
    v.z += b[col + 2];
    v.w += b[col + 3];
    Y[i] = v;
}

// ---------------------------------------------------------------------------
// Row softmax over SEQ=4096 with scale folded in; one block (256 thr) per row.
// ---------------------------------------------------------------------------
__global__ __launch_bounds__(256)
void softmax_kernel(float* __restrict__ S, float scale)
{
    long long row = blockIdx.x;
    float* p = S + row * (long long)SEQ;
    const int tid  = threadIdx.x;
    const int warp = tid >> 5;
    const int lane = tid & 31;

    __shared__ float red[8];
    __shared__ float bval;

    float v[16];
    float mx = -1e30f;
#pragma unroll
    for (int i = 0; i < 16; i++) {
        v[i] = p[i * 256 + tid] * scale;
        mx = fmaxf(mx, v[i]);
    }
#pragma unroll
    for (int o = 16; o > 0; o >>= 1)
        mx = fmaxf(mx, __shfl_xor_sync(0xffffffffu, mx, o));
    if (lane == 0) red[warp] = mx;
    __syncthreads();
    if (tid == 0) {
        float m = red[0];
#pragma unroll
        for (int i = 1; i < 8; i++) m = fmaxf(m, red[i]);
        bval = m;
    }
    __syncthreads();
    mx = bval;
    __syncthreads();   // everyone has read bval before it is rewritten

    float sum = 0.0f;
#pragma unroll
    for (int i = 0; i < 16; i++) {
        v[i] = __expf(v[i] - mx);
        sum += v[i];
    }
#pragma unroll
    for (int o = 16; o > 0; o >>= 1)
        sum += __shfl_xor_sync(0xffffffffu, sum, o);
    if (lane == 0) red[warp] = sum;
    __syncthreads();
    if (tid == 0) {
        float s = 0.0f;
#pragma unroll
        for (int i = 0; i < 8; i++) s += red[i];
        bval = s;
    }
    __syncthreads();
    float inv = 1.0f / bval;
#pragma unroll
    for (int i = 0; i < 16; i++)
        p[i * 256 + tid] = v[i] * inv;
}

// ---------------------------------------------------------------------------
// Launch
// ---------------------------------------------------------------------------
extern "C" void kernel_launch(void* const* d_in, const int* in_sizes, int n_in,
                              void* d_out, int out_size)
{
    const float* x  = (const float*)d_in[0];
    const float* Wq = (const float*)d_in[1];
    const float* bq = (const float*)d_in[2];
    const float* Wk = (const float*)d_in[3];
    const float* bk = (const float*)d_in[4];
    const float* Wv = (const float*)d_in[5];
    const float* bv = (const float*)d_in[6];
    float* out = (float*)d_out;

    float *Qp, *Kp, *Vp, *Sp;
    cudaGetSymbolAddress((void**)&Qp, g_Q);
    cudaGetSymbolAddress((void**)&Kp, g_K);
    cudaGetSymbolAddress((void**)&Vp, g_V);
    cudaGetSymbolAddress((void**)&Sp, g_S);

    const int M = BATCH * SEQ;                 // 16384
    const long long qkvStride = (long long)SEQ * HIDDEN;    // per-batch Q/K/V
    const long long sStride   = (long long)SEQ * SEQ;       // per-batch S

    // 1) QKV projections: [16384,768] = x @ W^T   (B stored [N,K] -> col layout)
    {
        dim3 grid(HIDDEN / BN, M / BM, 1);     // (6, 128)
        gemm_kernel<true><<<grid, 256>>>(x, Wq, Qp, M, HIDDEN, HIDDEN, 0, 0, 0);
        gemm_kernel<true><<<grid, 256>>>(x, Wk, Kp, M, HIDDEN, HIDDEN, 0, 0, 0);
        gemm_kernel<true><<<grid, 256>>>(x, Wv, Vp, M, HIDDEN, HIDDEN, 0, 0, 0);
    }

    // 2) bias add
    {
        int n4 = M * HIDDEN / 4;               // 3,145,728
        int blocks = (n4 + 255) / 256;
        bias_kernel<<<blocks, 256>>>((float4*)Qp, bq, n4);
        bias_kernel<<<blocks, 256>>>((float4*)Kp, bk, n4);
        bias_kernel<<<blocks, 256>>>((float4*)Vp, bv, n4);
    }

    // 3) scores: S_b = Q_b @ K_b^T   (K stored [S, H] -> col layout, ldb = K = 768)
    {
        dim3 grid(SEQ / BN, SEQ / BM, BATCH);  // (32, 32, 4)
        gemm_kernel<true><<<grid, 256>>>(Qp, Kp, Sp, SEQ, SEQ, HIDDEN,
                                         qkvStride, qkvStride, sStride);
    }

    // 4) softmax rows (scale folded in)
    {
        float scale = 1.0f / sqrtf((float)HIDDEN);
        softmax_kernel<<<BATCH * SEQ, 256>>>(Sp, scale);
    }

    // 5) output: O_b = P_b @ V_b    (V stored [K, N] row-major)
    {
        dim3 grid(HIDDEN / BN, SEQ / BM, BATCH);  // (6, 32, 4)
        gemm_kernel<false><<<grid, 256>>>(Sp, Vp, out, SEQ, HIDDEN, SEQ,
                                          sStride, qkvStride, qkvStride);
    }
}

// round 7
// speedup vs baseline: 1.5280x; 1.5280x over previous
#include <cuda_runtime.h>
#include <cstdint>
#include <mma.h>

using namespace nvcuda;

#define HIDDEN 768
#define BATCH  4
#define SEQ    4096

// ---- scratch (device globals: allocation-free rule) ----
__device__ float g_Q[BATCH * SEQ * HIDDEN];                 // 48 MB
__device__ float g_K[BATCH * SEQ * HIDDEN];                 // 48 MB
__device__ float g_V[BATCH * SEQ * HIDDEN];                 // 48 MB
__device__ float g_S[(long long)BATCH * SEQ * SEQ];         // 256 MB

// ---------------------------------------------------------------------------
// TF32 wmma GEMM, cp.async double-buffered:  C = A @ B (+ bias)
//   A: row-major [M,K]
//   B_COL=true : B stored [N,K] row-major (logical B[k,n] = Bmem[n*K+k])
//   B_COL=false: B stored [K,N] row-major (logical B[k,n] = Bmem[k*N+n])
// Block tile 128x128x32, 256 threads (8 warps, 2x4), warp tile 64x32.
// ---------------------------------------------------------------------------
constexpr int BM = 128, BN = 128, BK = 32;
constexpr int BKP = 36;   // padded ld for k-contiguous smem tiles
constexpr int BNP = 132;  // padded ld for n-contiguous smem tiles

constexpr int A_TILE_F = BM * BKP;            // 4608 floats
constexpr int B_TILE_F = BM * BKP;            // 4608 floats (covers 32*132=4224 too)
constexpr int STAGE_F  = A_TILE_F + B_TILE_F; // 9216 floats
constexpr int SMEM_F   = 2 * STAGE_F;         // 18432 floats = 73728 bytes

__device__ __forceinline__ void cp_async16(void* sdst, const void* gsrc) {
    unsigned int s = (unsigned int)__cvta_generic_to_shared(sdst);
    asm volatile("cp.async.cg.shared.global [%0], [%1], 16;\n"
                 :: "r"(s), "l"(gsrc));
}
__device__ __forceinline__ void cp_commit() {
    asm volatile("cp.async.commit_group;\n");
}
template <int N_>
__device__ __forceinline__ void cp_wait() {
    asm volatile("cp.async.wait_group %0;\n" :: "n"(N_));
}

template <bool B_COL>
__global__ __launch_bounds__(256, 2)
void gemm_kernel(const float* __restrict__ A,
                 const float* __restrict__ B,
                 float* __restrict__ C,
                 const float* __restrict__ bias,   // nullable
                 int M, int N, int K,
                 long long strideA, long long strideB, long long strideC)
{
    extern __shared__ float smem[];

    A += (long long)blockIdx.z * strideA;
    B += (long long)blockIdx.z * strideB;
    C += (long long)blockIdx.z * strideC;

    const int m0 = blockIdx.y * BM;
    const int n0 = blockIdx.x * BN;
    const int tid  = threadIdx.x;
    const int warp = tid >> 5;
    const int lane = tid & 31;
    const int wm = (warp >> 2) * 64;     // warp row offset: 0 / 64
    const int wn = (warp & 3) * 32;      // warp col offset: 0/32/64/96

    wmma::fragment<wmma::accumulator, 16, 16, 8, float> acc[4][2];
#pragma unroll
    for (int i = 0; i < 4; i++)
#pragma unroll
        for (int j = 0; j < 2; j++)
            wmma::fill_fragment(acc[i][j], 0.0f);

    // ---- async tile loader ----
    auto loadTiles = [&](int stage, int k0) {
        float* As = smem + stage * STAGE_F;
        float* Bs = As + A_TILE_F;
#pragma unroll
        for (int i = 0; i < 4; i++) {
            int idx = tid + i * 256;
            int r = idx >> 3;
            int c = (idx & 7) << 2;
            cp_async16(&As[r * BKP + c],
                       A + (long long)(m0 + r) * K + k0 + c);
        }
        if (B_COL) {
#pragma unroll
            for (int i = 0; i < 4; i++) {
                int idx = tid + i * 256;
                int r = idx >> 3;           // n within tile
                int c = (idx & 7) << 2;     // k within tile
                cp_async16(&Bs[r * BKP + c],
                           B + (long long)(n0 + r) * K + k0 + c);
            }
        } else {
#pragma unroll
            for (int i = 0; i < 4; i++) {
                int idx = tid + i * 256;
                int r = idx >> 5;           // k within tile (0..31)
                int c = (idx & 31) << 2;    // n within tile
                cp_async16(&Bs[r * BNP + c],
                           B + (long long)(k0 + r) * N + n0 + c);
            }
        }
        cp_commit();
    };

    const int numT = K / BK;
    loadTiles(0, 0);
    int cur = 0;

    for (int t = 0; t < numT; t++) {
        if (t + 1 < numT) {
            loadTiles(cur ^ 1, (t + 1) * BK);
            cp_wait<1>();                  // tile t complete; prefetch in flight
        } else {
            cp_wait<0>();
        }
        __syncthreads();

        const float* As = smem + cur * STAGE_F;
        const float* Bs = As + A_TILE_F;

#pragma unroll
        for (int kk = 0; kk < BK; kk += 8) {
            wmma::fragment<wmma::matrix_a, 16, 16, 8,
                           wmma::precision::tf32, wmma::row_major> af[4];
#pragma unroll
            for (int i = 0; i < 4; i++) {
                wmma::load_matrix_sync(af[i], &As[(wm + i * 16) * BKP + kk], BKP);
#pragma unroll
                for (int e = 0; e < af[i].num_elements; e++)
                    af[i].x[e] = wmma::__float_to_tf32(af[i].x[e]);
            }
            if constexpr (B_COL) {
                wmma::fragment<wmma::matrix_b, 16, 16, 8,
                               wmma::precision::tf32, wmma::col_major> bf[2];
#pragma unroll
                for (int j = 0; j < 2; j++) {
                    wmma::load_matrix_sync(bf[j], &Bs[(wn + j * 16) * BKP + kk], BKP);
#pragma unroll
                    for (int e = 0; e < bf[j].num_elements; e++)
                        bf[j].x[e] = wmma::__float_to_tf32(bf[j].x[e]);
                }
#pragma unroll
                for (int i = 0; i < 4; i++)
#pragma unroll
                    for (int j = 0; j < 2; j++)
                        wmma::mma_sync(acc[i][j], af[i], bf[j], acc[i][j]);
            } else {
                wmma::fragment<wmma::matrix_b, 16, 16, 8,
                               wmma::precision::tf32, wmma::row_major> bf[2];
#pragma unroll
                for (int j = 0; j < 2; j++) {
                    wmma::load_matrix_sync(bf[j], &Bs[kk * BNP + wn + j * 16], BNP);
#pragma unroll
                    for (int e = 0; e < bf[j].num_elements; e++)
                        bf[j].x[e] = wmma::__float_to_tf32(bf[j].x[e]);
                }
#pragma unroll
                for (int i = 0; i < 4; i++)
#pragma unroll
                    for (int j = 0; j < 2; j++)
                        wmma::mma_sync(acc[i][j], af[i], bf[j], acc[i][j]);
            }
        }
        __syncthreads();
        cur ^= 1;
    }

    // ---- epilogue: stage through smem, fuse bias, coalesced 128B row writes ----
    // Per warp: 64x32 tile at ld 36 -> 2304 floats; 8 warps = 18432 = SMEM_F.
    float* Cs = smem + warp * (64 * 36);
#pragma unroll
    for (int i = 0; i < 4; i++)
#pragma unroll
        for (int j = 0; j < 2; j++)
            wmma::store_matrix_sync(&Cs[(i * 16) * 36 + j * 16], acc[i][j],
                                    36, wmma::mem_row_major);
    __syncwarp();

    const float bv = bias ? bias[n0 + wn + lane] : 0.0f;
    float* Cout = C + (long long)(m0 + wm) * N + n0 + wn + lane;
#pragma unroll 8
    for (int r = 0; r < 64; r++)
        Cout[(long long)r * N] = Cs[r * 36 + lane] + bv;
}

// ---------------------------------------------------------------------------
// Row softmax over SEQ=4096 with scale folded in; one block (256 thr) per row.
// ---------------------------------------------------------------------------
__global__ __launch_bounds__(256)
void softmax_kernel(float* __restrict__ S, float scale)
{
    long long row = blockIdx.x;
    float* p = S + row * (long long)SEQ;
    const int tid  = threadIdx.x;
    const int warp = tid >> 5;
    const int lane = tid & 31;

    __shared__ float red[8];
    __shared__ float bval;

    float v[16];
    float mx = -1e30f;
#pragma unroll
    for (int i = 0; i < 16; i++) {
        v[i] = p[i * 256 + tid] * scale;
        mx = fmaxf(mx, v[i]);
    }
#pragma unroll
    for (int o = 16; o > 0; o >>= 1)
        mx = fmaxf(mx, __shfl_xor_sync(0xffffffffu, mx, o));
    if (lane == 0) red[warp] = mx;
    __syncthreads();
    if (tid == 0) {
        float m = red[0];
#pragma unroll
        for (int i = 1; i < 8; i++) m = fmaxf(m, red[i]);
        bval = m;
    }
    __syncthreads();
    mx = bval;
    __syncthreads();

    float sum = 0.0f;
#pragma unroll
    for (int i = 0; i < 16; i++) {
        v[i] = __expf(v[i] - mx);
        sum += v[i];
    }
#pragma unroll
    for (int o = 16; o > 0; o >>= 1)
        sum += __shfl_xor_sync(0xffffffffu, sum, o);
    if (lane == 0) red[warp] = sum;
    __syncthreads();
    if (tid == 0) {
        float s = 0.0f;
#pragma unroll
        for (int i = 0; i < 8; i++) s += red[i];
        bval = s;
    }
    __syncthreads();
    float inv = 1.0f / bval;
#pragma unroll
    for (int i = 0; i < 16; i++)
        p[i * 256 + tid] = v[i] * inv;
}

// ---------------------------------------------------------------------------
// Launch
// ---------------------------------------------------------------------------
extern "C" void kernel_launch(void* const* d_in, const int* in_sizes, int n_in,
                              void* d_out, int out_size)
{
    const float* x  = (const float*)d_in[0];
    const float* Wq = (const float*)d_in[1];
    const float* bq = (const float*)d_in[2];
    const float* Wk = (const float*)d_in[3];
    const float* bk = (const float*)d_in[4];
    const float* Wv = (const float*)d_in[5];
    const float* bv = (const float*)d_in[6];
    float* out = (float*)d_out;

    float *Qp, *Kp, *Vp, *Sp;
    cudaGetSymbolAddress((void**)&Qp, g_Q);
    cudaGetSymbolAddress((void**)&Kp, g_K);
    cudaGetSymbolAddress((void**)&Vp, g_V);
    cudaGetSymbolAddress((void**)&Sp, g_S);

    const int smemBytes = SMEM_F * (int)sizeof(float);   // 73728
    cudaFuncSetAttribute(gemm_kernel<true>,
                         cudaFuncAttributeMaxDynamicSharedMemorySize, smemBytes);
    cudaFuncSetAttribute(gemm_kernel<false>,
                         cudaFuncAttributeMaxDynamicSharedMemorySize, smemBytes);

    const int M = BATCH * SEQ;                              // 16384
    const long long qkvStride = (long long)SEQ * HIDDEN;    // per-batch Q/K/V
    const long long sStride   = (long long)SEQ * SEQ;       // per-batch S

    // 1) QKV projections with fused bias: [16384,768] = x @ W^T + b
    {
        dim3 grid(HIDDEN / BN, M / BM, 1);     // (6, 128)
        gemm_kernel<true><<<grid, 256, smemBytes>>>(x, Wq, Qp, bq, M, HIDDEN, HIDDEN, 0, 0, 0);
        gemm_kernel<true><<<grid, 256, smemBytes>>>(x, Wk, Kp, bk, M, HIDDEN, HIDDEN, 0, 0, 0);
        gemm_kernel<true><<<grid, 256, smemBytes>>>(x, Wv, Vp, bv, M, HIDDEN, HIDDEN, 0, 0, 0);
    }

    // 2) scores: S_b = Q_b @ K_b^T
    {
        dim3 grid(SEQ / BN, SEQ / BM, BATCH);  // (32, 32, 4)
        gemm_kernel<true><<<grid, 256, smemBytes>>>(Qp, Kp, Sp, nullptr,
                                                    SEQ, SEQ, HIDDEN,
                                                    qkvStride, qkvStride, sStride);
    }

    // 3) softmax rows (scale folded in)
    {
        float scale = 1.0f / sqrtf((float)HIDDEN);
        softmax_kernel<<<BATCH * SEQ, 256>>>(Sp, scale);
    }

    // 4) output: O_b = P_b @ V_b
    {
        dim3 grid(HIDDEN / BN, SEQ / BM, BATCH);  // (6, 32, 4)
        gemm_kernel<false><<<grid, 256, smemBytes>>>(Sp, Vp, out, nullptr,
                                                     SEQ, HIDDEN, SEQ,
                                                     sStride, qkvStride, qkvStride);
    }
}